// round 11
// baseline (speedup 1.0000x reference)
#include <cuda_runtime.h>

#define NN 100000
#define NE 1600000
#define HID 128
#define OUTC 10
#define NG 512
#define SCAN_B 1024
#define NBLK ((NN + SCAN_B - 1) / SCAN_B)   // 98

// Scratch (device globals — no allocation allowed)
__device__ float g_z[(size_t)NN * HID];
__device__ float g_y[(size_t)NN * HID];
__device__ float g_h[(size_t)NN * HID];
__device__ float g_pool[NG * HID];
__device__ int   g_deg[NN];
__device__ int   g_rptr[NN + 1];
__device__ int   g_cursor[NN];
__device__ int   g_partials[NBLK];
__device__ int   g_csr_src[NE];

// ================= CSR build =================
__global__ void deg_zero() {
    int i = blockIdx.x * blockDim.x + threadIdx.x;
    if (i < NN) g_deg[i] = 0;
}

__global__ void deg_hist(const int* __restrict__ ei) {
    int e = blockIdx.x * blockDim.x + threadIdx.x;
    if (e < NE) atomicAdd(&g_deg[ei[NE + e]], 1);
}

// Exclusive block scan (Hillis-Steele), 1024 threads per block.
__global__ void scan_block() {
    __shared__ int sh[SCAN_B];
    int i = blockIdx.x * SCAN_B + threadIdx.x;
    int v = (i < NN) ? g_deg[i] : 0;
    sh[threadIdx.x] = v;
    __syncthreads();
#pragma unroll
    for (int off = 1; off < SCAN_B; off <<= 1) {
        int t = (threadIdx.x >= off) ? sh[threadIdx.x - off] : 0;
        __syncthreads();
        sh[threadIdx.x] += t;
        __syncthreads();
    }
    if (i < NN) g_rptr[i] = sh[threadIdx.x] - v;   // exclusive
    if (threadIdx.x == SCAN_B - 1) g_partials[blockIdx.x] = sh[SCAN_B - 1];
}

__global__ void scan_partials() {
    if (threadIdx.x == 0) {
        int acc = 0;
        for (int b = 0; b < NBLK; b++) { int t = g_partials[b]; g_partials[b] = acc; acc += t; }
    }
}

__global__ void scan_add() {
    int i = blockIdx.x * SCAN_B + threadIdx.x;
    if (i < NN) {
        int v = g_rptr[i] + g_partials[blockIdx.x];
        g_rptr[i] = v;
        g_cursor[i] = v;
    }
    if (i == 0) g_rptr[NN] = NE;
}

__global__ void scatter_edges(const int* __restrict__ ei) {
    int e = blockIdx.x * blockDim.x + threadIdx.x;
    if (e >= NE) return;
    int s = ei[e];
    int d = ei[NE + e];
    int pos = atomicAdd(&g_cursor[d], 1);
    g_csr_src[pos] = s;
}

// ================= CSR aggregation: z[i] = h[i] + sum_{j in N(i)} h[j] =================
// One warp per dst node; lane handles channels 4*lane..4*lane+3.
__global__ void __launch_bounds__(256)
agg_csr(const float* __restrict__ h, float* __restrict__ z) {
    int gid  = blockIdx.x * blockDim.x + threadIdx.x;
    int node = gid >> 5;
    int lane = gid & 31;
    if (node >= NN) return;

    int beg = g_rptr[node];
    int end = g_rptr[node + 1];

    float4 acc = *(const float4*)(h + (size_t)node * HID + lane * 4);

    for (int j = beg; j < end; j += 32) {
        int sv = (j + lane < end) ? g_csr_src[j + lane] : 0;
        int cnt = min(32, end - j);
        for (int i = 0; i < cnt; i++) {
            int s = __shfl_sync(0xffffffffu, sv, i);
            float4 v = *(const float4*)(h + (size_t)s * HID + lane * 4);
            acc.x += v.x; acc.y += v.y; acc.z += v.z; acc.w += v.w;
        }
    }
    *(float4*)(z + (size_t)node * HID + lane * 4) = acc;
}

// ================= GEMM: C[M,128] = act(A[M,128] @ W[128,128] + b) =================
template <bool RELU>
__global__ void __launch_bounds__(256, 2)
gemm128(const float* __restrict__ A, const float* __restrict__ W,
        const float* __restrict__ bias, float* __restrict__ C, int M) {
    __shared__ float As[128][20];
    __shared__ float Ws[16][128];

    int t  = threadIdx.x;
    int tx = t & 15;
    int ty = t >> 4;
    int r0 = blockIdx.x * 128;

    float acc[8][8];
#pragma unroll
    for (int i = 0; i < 8; i++)
#pragma unroll
        for (int j = 0; j < 8; j++) acc[i][j] = 0.f;

    for (int k0 = 0; k0 < 128; k0 += 16) {
#pragma unroll
        for (int i = 0; i < 2; i++) {
            int idx = t + i * 256;
            int row = idx >> 2;
            int c4  = (idx & 3) * 4;
            int gr  = r0 + row;
            float4 v = make_float4(0.f, 0.f, 0.f, 0.f);
            if (gr < M) v = *(const float4*)(A + (size_t)gr * 128 + k0 + c4);
            *(float4*)&As[row][c4] = v;
        }
#pragma unroll
        for (int i = 0; i < 2; i++) {
            int idx = t + i * 256;
            int kk  = idx >> 5;
            int c4  = (idx & 31) * 4;
            *(float4*)&Ws[kk][c4] = *(const float4*)(W + (size_t)(k0 + kk) * 128 + c4);
        }
        __syncthreads();

#pragma unroll
        for (int kk = 0; kk < 16; kk++) {
            float a[8], b[8];
#pragma unroll
            for (int i = 0; i < 8; i++) a[i] = As[8 * ty + i][kk];
            *(float4*)&b[0] = *(float4*)&Ws[kk][8 * tx];
            *(float4*)&b[4] = *(float4*)&Ws[kk][8 * tx + 4];
#pragma unroll
            for (int i = 0; i < 8; i++)
#pragma unroll
                for (int j = 0; j < 8; j++) acc[i][j] += a[i] * b[j];
        }
        __syncthreads();
    }

    float bfr[8];
#pragma unroll
    for (int j = 0; j < 8; j++) bfr[j] = bias[8 * tx + j];

#pragma unroll
    for (int i = 0; i < 8; i++) {
        int gr = r0 + 8 * ty + i;
        if (gr < M) {
            float v[8];
#pragma unroll
            for (int j = 0; j < 8; j++) {
                float x = acc[i][j] + bfr[j];
                if (RELU) x = fmaxf(x, 0.f);
                v[j] = x;
            }
            *(float4*)(C + (size_t)gr * 128 + 8 * tx)     = make_float4(v[0], v[1], v[2], v[3]);
            *(float4*)(C + (size_t)gr * 128 + 8 * tx + 4) = make_float4(v[4], v[5], v[6], v[7]);
        }
    }
}

// ================= pooling =================
__global__ void pool_zero() {
    int i = blockIdx.x * blockDim.x + threadIdx.x;
    if (i < NG * HID) g_pool[i] = 0.f;
}

__global__ void pool_add(const int* __restrict__ batch,
                         const float* __restrict__ h) {
    long long gid = (long long)blockIdx.x * blockDim.x + threadIdx.x;
    int node = (int)(gid >> 5);
    int lane = (int)(gid & 31);
    if (node >= NN) return;
    int b = 0;
    if (lane == 0) b = batch[node];
    b = __shfl_sync(0xffffffffu, b, 0);
    float4 v = *(const float4*)(h + (size_t)node * HID + lane * 4);
    float* pp = g_pool + (size_t)b * HID + lane * 4;
    atomicAdd(pp + 0, v.x);
    atomicAdd(pp + 1, v.y);
    atomicAdd(pp + 2, v.z);
    atomicAdd(pp + 3, v.w);
}

// ================= final linear =================
__global__ void final_lin(const float* __restrict__ W,
                          const float* __restrict__ b,
                          float* __restrict__ out) {
    int i = blockIdx.x * blockDim.x + threadIdx.x;
    if (i >= NG * OUTC) return;
    int g = i / OUTC, o = i % OUTC;
    float acc = b[o];
    const float* p = g_pool + (size_t)g * HID;
#pragma unroll
    for (int k = 0; k < HID; k++) acc += p[k] * W[k * OUTC + o];
    out[i] = acc;
}

extern "C" void kernel_launch(void* const* d_in, const int* in_sizes, int n_in,
                              void* d_out, int out_size) {
    const float* x     = (const float*)d_in[0];
    const int*   ei    = (const int*)d_in[1];
    const int*   batch = (const int*)d_in[2];
    const float* w1[3] = { (const float*)d_in[3],  (const float*)d_in[7],  (const float*)d_in[11] };
    const float* b1[3] = { (const float*)d_in[4],  (const float*)d_in[8],  (const float*)d_in[12] };
    const float* w2[3] = { (const float*)d_in[5],  (const float*)d_in[9],  (const float*)d_in[13] };
    const float* b2[3] = { (const float*)d_in[6],  (const float*)d_in[10], (const float*)d_in[14] };
    const float* lin_w = (const float*)d_in[15];
    const float* lin_b = (const float*)d_in[16];
    float* out = (float*)d_out;

    float *pz, *py, *ph;
    cudaGetSymbolAddress((void**)&pz, g_z);
    cudaGetSymbolAddress((void**)&py, g_y);
    cudaGetSymbolAddress((void**)&ph, g_h);

    // ---- build dst-CSR once per launch ----
    deg_zero<<<(NN + 255) / 256, 256>>>();
    deg_hist<<<(NE + 255) / 256, 256>>>(ei);
    scan_block<<<NBLK, SCAN_B>>>();
    scan_partials<<<1, 32>>>();
    scan_add<<<NBLK, SCAN_B>>>();
    scatter_edges<<<(NE + 255) / 256, 256>>>(ei);

    const int agg_grid  = (NN * 32 + 255) / 256;
    const int gemm_grid = (NN + 127) / 128;

    const float* hin = x;
    for (int l = 0; l < 3; l++) {
        // z = h + sum_neighbors h  (copy folded in)
        agg_csr<<<agg_grid, 256>>>(hin, pz);
        // y = relu(z @ w1 + b1)
        gemm128<true><<<gemm_grid, 256>>>(pz, w1[l], b1[l], py, NN);
        // h = y @ w2 + b2 (+ inter-layer relu for l<2)
        if (l < 2) gemm128<true><<<gemm_grid, 256>>>(py, w2[l], b2[l], ph, NN);
        else       gemm128<false><<<gemm_grid, 256>>>(py, w2[l], b2[l], ph, NN);
        hin = ph;
    }

    // global_add_pool
    pool_zero<<<(NG * HID + 255) / 256, 256>>>();
    pool_add<<<(NN * 32 + 255) / 256, 256>>>(batch, ph);

    // final linear
    final_lin<<<(NG * OUTC + 255) / 256, 256>>>(lin_w, lin_b, out);
}

// round 12
// speedup vs baseline: 1.0049x; 1.0049x over previous
#include <cuda_runtime.h>

#define NN 100000
#define NE 1600000
#define HID 128
#define OUTC 10
#define NG 512
#define SCAN_B 1024
#define NBLK ((NN + SCAN_B - 1) / SCAN_B)   // 98

// Scratch (device globals — no allocation allowed)
__device__ float g_z[(size_t)NN * HID];
__device__ float g_y[(size_t)NN * HID];
__device__ float g_h[(size_t)NN * HID];
__device__ float g_pool[NG * HID];
__device__ int   g_deg[NN];
__device__ int   g_rptr[NN + 1];
__device__ int   g_cursor[NN];
__device__ int   g_partials[NBLK];
__device__ int   g_csr_src[NE];

// ================= CSR build =================
__global__ void deg_zero() {
    int i = blockIdx.x * blockDim.x + threadIdx.x;
    if (i < NN) g_deg[i] = 0;
}

__global__ void deg_hist(const int* __restrict__ ei) {
    int e = blockIdx.x * blockDim.x + threadIdx.x;
    if (e < NE) atomicAdd(&g_deg[ei[NE + e]], 1);
}

// Exclusive block scan (Hillis-Steele), 1024 threads per block.
__global__ void scan_block() {
    __shared__ int sh[SCAN_B];
    int i = blockIdx.x * SCAN_B + threadIdx.x;
    int v = (i < NN) ? g_deg[i] : 0;
    sh[threadIdx.x] = v;
    __syncthreads();
#pragma unroll
    for (int off = 1; off < SCAN_B; off <<= 1) {
        int t = (threadIdx.x >= off) ? sh[threadIdx.x - off] : 0;
        __syncthreads();
        sh[threadIdx.x] += t;
        __syncthreads();
    }
    if (i < NN) g_rptr[i] = sh[threadIdx.x] - v;   // exclusive
    if (threadIdx.x == SCAN_B - 1) g_partials[blockIdx.x] = sh[SCAN_B - 1];
}

__global__ void scan_partials() {
    if (threadIdx.x == 0) {
        int acc = 0;
        for (int b = 0; b < NBLK; b++) { int t = g_partials[b]; g_partials[b] = acc; acc += t; }
    }
}

__global__ void scan_add() {
    int i = blockIdx.x * SCAN_B + threadIdx.x;
    if (i < NN) {
        int v = g_rptr[i] + g_partials[blockIdx.x];
        g_rptr[i] = v;
        g_cursor[i] = v;
    }
    if (i == 0) g_rptr[NN] = NE;
}

__global__ void scatter_edges(const int* __restrict__ ei) {
    int e = blockIdx.x * blockDim.x + threadIdx.x;
    if (e >= NE) return;
    int s = ei[e];
    int d = ei[NE + e];
    int pos = atomicAdd(&g_cursor[d], 1);
    g_csr_src[pos] = s;
}

// ================= CSR aggregation: z[i] = h[i] + sum_{j in N(i)} h[j] =================
// One warp per dst node; lane handles channels 4*lane..4*lane+3.
__global__ void __launch_bounds__(256)
agg_csr(const float* __restrict__ h, float* __restrict__ z) {
    int gid  = blockIdx.x * blockDim.x + threadIdx.x;
    int node = gid >> 5;
    int lane = gid & 31;
    if (node >= NN) return;

    int beg = g_rptr[node];
    int end = g_rptr[node + 1];

    float4 acc = *(const float4*)(h + (size_t)node * HID + lane * 4);

    for (int j = beg; j < end; j += 32) {
        int sv = (j + lane < end) ? g_csr_src[j + lane] : 0;
        int cnt = min(32, end - j);
        for (int i = 0; i < cnt; i++) {
            int s = __shfl_sync(0xffffffffu, sv, i);
            float4 v = *(const float4*)(h + (size_t)s * HID + lane * 4);
            acc.x += v.x; acc.y += v.y; acc.z += v.z; acc.w += v.w;
        }
    }
    *(float4*)(z + (size_t)node * HID + lane * 4) = acc;
}

// ================= GEMM: C[M,128] = act(A[M,128] @ W[128,128] + b) =================
template <bool RELU>
__global__ void __launch_bounds__(256, 2)
gemm128(const float* __restrict__ A, const float* __restrict__ W,
        const float* __restrict__ bias, float* __restrict__ C, int M) {
    __shared__ float As[128][20];
    __shared__ float Ws[16][128];

    int t  = threadIdx.x;
    int tx = t & 15;
    int ty = t >> 4;
    int r0 = blockIdx.x * 128;

    float acc[8][8];
#pragma unroll
    for (int i = 0; i < 8; i++)
#pragma unroll
        for (int j = 0; j < 8; j++) acc[i][j] = 0.f;

    for (int k0 = 0; k0 < 128; k0 += 16) {
#pragma unroll
        for (int i = 0; i < 2; i++) {
            int idx = t + i * 256;
            int row = idx >> 2;
            int c4  = (idx & 3) * 4;
            int gr  = r0 + row;
            float4 v = make_float4(0.f, 0.f, 0.f, 0.f);
            if (gr < M) v = *(const float4*)(A + (size_t)gr * 128 + k0 + c4);
            *(float4*)&As[row][c4] = v;
        }
#pragma unroll
        for (int i = 0; i < 2; i++) {
            int idx = t + i * 256;
            int kk  = idx >> 5;
            int c4  = (idx & 31) * 4;
            *(float4*)&Ws[kk][c4] = *(const float4*)(W + (size_t)(k0 + kk) * 128 + c4);
        }
        __syncthreads();

#pragma unroll
        for (int kk = 0; kk < 16; kk++) {
            float a[8], b[8];
#pragma unroll
            for (int i = 0; i < 8; i++) a[i] = As[8 * ty + i][kk];
            *(float4*)&b[0] = *(float4*)&Ws[kk][8 * tx];
            *(float4*)&b[4] = *(float4*)&Ws[kk][8 * tx + 4];
#pragma unroll
            for (int i = 0; i < 8; i++)
#pragma unroll
                for (int j = 0; j < 8; j++) acc[i][j] += a[i] * b[j];
        }
        __syncthreads();
    }

    float bfr[8];
#pragma unroll
    for (int j = 0; j < 8; j++) bfr[j] = bias[8 * tx + j];

#pragma unroll
    for (int i = 0; i < 8; i++) {
        int gr = r0 + 8 * ty + i;
        if (gr < M) {
            float v[8];
#pragma unroll
            for (int j = 0; j < 8; j++) {
                float x = acc[i][j] + bfr[j];
                if (RELU) x = fmaxf(x, 0.f);
                v[j] = x;
            }
            *(float4*)(C + (size_t)gr * 128 + 8 * tx)     = make_float4(v[0], v[1], v[2], v[3]);
            *(float4*)(C + (size_t)gr * 128 + 8 * tx + 4) = make_float4(v[4], v[5], v[6], v[7]);
        }
    }
}

// ================= pooling =================
__global__ void pool_zero() {
    int i = blockIdx.x * blockDim.x + threadIdx.x;
    if (i < NG * HID) g_pool[i] = 0.f;
}

__global__ void pool_add(const int* __restrict__ batch,
                         const float* __restrict__ h) {
    long long gid = (long long)blockIdx.x * blockDim.x + threadIdx.x;
    int node = (int)(gid >> 5);
    int lane = (int)(gid & 31);
    if (node >= NN) return;
    int b = 0;
    if (lane == 0) b = batch[node];
    b = __shfl_sync(0xffffffffu, b, 0);
    float4 v = *(const float4*)(h + (size_t)node * HID + lane * 4);
    float* pp = g_pool + (size_t)b * HID + lane * 4;
    atomicAdd(pp + 0, v.x);
    atomicAdd(pp + 1, v.y);
    atomicAdd(pp + 2, v.z);
    atomicAdd(pp + 3, v.w);
}

// ================= final linear =================
__global__ void final_lin(const float* __restrict__ W,
                          const float* __restrict__ b,
                          float* __restrict__ out) {
    int i = blockIdx.x * blockDim.x + threadIdx.x;
    if (i >= NG * OUTC) return;
    int g = i / OUTC, o = i % OUTC;
    float acc = b[o];
    const float* p = g_pool + (size_t)g * HID;
#pragma unroll
    for (int k = 0; k < HID; k++) acc += p[k] * W[k * OUTC + o];
    out[i] = acc;
}

extern "C" void kernel_launch(void* const* d_in, const int* in_sizes, int n_in,
                              void* d_out, int out_size) {
    const float* x     = (const float*)d_in[0];
    const int*   ei    = (const int*)d_in[1];
    const int*   batch = (const int*)d_in[2];
    const float* w1[3] = { (const float*)d_in[3],  (const float*)d_in[7],  (const float*)d_in[11] };
    const float* b1[3] = { (const float*)d_in[4],  (const float*)d_in[8],  (const float*)d_in[12] };
    const float* w2[3] = { (const float*)d_in[5],  (const float*)d_in[9],  (const float*)d_in[13] };
    const float* b2[3] = { (const float*)d_in[6],  (const float*)d_in[10], (const float*)d_in[14] };
    const float* lin_w = (const float*)d_in[15];
    const float* lin_b = (const float*)d_in[16];
    float* out = (float*)d_out;

    float *pz, *py, *ph;
    cudaGetSymbolAddress((void**)&pz, g_z);
    cudaGetSymbolAddress((void**)&py, g_y);
    cudaGetSymbolAddress((void**)&ph, g_h);

    // ---- build dst-CSR once per launch ----
    deg_zero<<<(NN + 255) / 256, 256>>>();
    deg_hist<<<(NE + 255) / 256, 256>>>(ei);
    scan_block<<<NBLK, SCAN_B>>>();
    scan_partials<<<1, 32>>>();
    scan_add<<<NBLK, SCAN_B>>>();
    scatter_edges<<<(NE + 255) / 256, 256>>>(ei);

    const int agg_grid  = (NN * 32 + 255) / 256;
    const int gemm_grid = (NN + 127) / 128;

    const float* hin = x;
    for (int l = 0; l < 3; l++) {
        // z = h + sum_neighbors h  (copy folded in)
        agg_csr<<<agg_grid, 256>>>(hin, pz);
        // y = relu(z @ w1 + b1)
        gemm128<true><<<gemm_grid, 256>>>(pz, w1[l], b1[l], py, NN);
        // h = y @ w2 + b2 (+ inter-layer relu for l<2)
        if (l < 2) gemm128<true><<<gemm_grid, 256>>>(py, w2[l], b2[l], ph, NN);
        else       gemm128<false><<<gemm_grid, 256>>>(py, w2[l], b2[l], ph, NN);
        hin = ph;
    }

    // global_add_pool
    pool_zero<<<(NG * HID + 255) / 256, 256>>>();
    pool_add<<<(NN * 32 + 255) / 256, 256>>>(batch, ph);

    // final linear
    final_lin<<<(NG * OUTC + 255) / 256, 256>>>(lin_w, lin_b, out);
}